// round 8
// baseline (speedup 1.0000x reference)
#include <cuda_runtime.h>
#include <cstdint>

#define NB     8
#define NPOS   21824
#define NG     (NPOS / 4)
#define NCLS   80
#define KTOP   1000
#define NBIN   8192
#define CAP    2048
#define IOU_TH 0.5f
#define MPITCH 33

// ---------------- scratch ----------------
__device__ __align__(16) float g_score[NB * NPOS];
__device__ __align__(16) int   g_kind [NB * NPOS];
__device__ float4              g_boxes[NB * NPOS];
__device__ unsigned            g_hist [NB * NBIN];   // zero at load; k_select re-zeros
__device__ float4              g_topBox  [NB * KTOP];
__device__ int                 g_topKind [NB * KTOP];
__device__ float               g_topScore[NB * KTOP];

// ---------------- K1: class max/argmax + decode + global score histogram -----
__global__ void k_decode(
    const float* __restrict__ c0, const float* __restrict__ c1,
    const float* __restrict__ c2, const float* __restrict__ c3,
    const float* __restrict__ c4,
    const float* __restrict__ r0, const float* __restrict__ r1,
    const float* __restrict__ r2, const float* __restrict__ r3,
    const float* __restrict__ r4)
{
    int g = blockIdx.x * blockDim.x + threadIdx.x;
    if (g >= NG) return;
    int b   = blockIdx.y;
    int pos = g << 2;

    int lvl, local, logw;
    float stride;
    if      (pos < 16384) { lvl = 0; local = pos;         logw = 7; stride = 8.f;   }
    else if (pos < 20480) { lvl = 1; local = pos - 16384; logw = 6; stride = 16.f;  }
    else if (pos < 21504) { lvl = 2; local = pos - 20480; logw = 5; stride = 32.f;  }
    else if (pos < 21760) { lvl = 3; local = pos - 21504; logw = 4; stride = 64.f;  }
    else                  { lvl = 4; local = pos - 21760; logw = 3; stride = 128.f; }
    int hw    = 1 << (2 * logw);
    int cstep = hw >> 2;

    const float* clsA[5] = { c0, c1, c2, c3, c4 };
    const float* regA[5] = { r0, r1, r2, r3, r4 };

    const float4* cls = (const float4*)(clsA[lvl] + (size_t)b * NCLS * hw + local);
    float4 bv = cls[0];
    int k0 = 0, k1 = 0, k2 = 0, k3 = 0;
    #pragma unroll 8
    for (int c = 1; c < NCLS; c++) {
        float4 v = cls[(size_t)c * cstep];
        if (v.x > bv.x) { bv.x = v.x; k0 = c; }
        if (v.y > bv.y) { bv.y = v.y; k1 = c; }
        if (v.z > bv.z) { bv.z = v.z; k2 = c; }
        if (v.w > bv.w) { bv.w = v.w; k3 = c; }
    }

    const float4* rg = (const float4*)(regA[lvl] + (size_t)b * 4 * hw + local);
    float4 dl4 = rg[0];
    float4 dt4 = rg[cstep];
    float4 dr4 = rg[2 * cstep];
    float4 db4 = rg[3 * cstep];

    int w = 1 << logw;
    int y = local >> logw;
    int x = local & (w - 1);
    float cy = ((float)y + 0.5f) * stride;

    int o = b * NPOS + pos;
    {
        float cx = ((float)(x + 0) + 0.5f) * stride;
        g_boxes[o + 0] = make_float4(cx - dl4.x * stride, cy - dt4.x * stride,
                                     cx + dr4.x * stride, cy + db4.x * stride);
        cx = ((float)(x + 1) + 0.5f) * stride;
        g_boxes[o + 1] = make_float4(cx - dl4.y * stride, cy - dt4.y * stride,
                                     cx + dr4.y * stride, cy + db4.y * stride);
        cx = ((float)(x + 2) + 0.5f) * stride;
        g_boxes[o + 2] = make_float4(cx - dl4.z * stride, cy - dt4.z * stride,
                                     cx + dr4.z * stride, cy + db4.z * stride);
        cx = ((float)(x + 3) + 0.5f) * stride;
        g_boxes[o + 3] = make_float4(cx - dl4.w * stride, cy - dt4.w * stride,
                                     cx + dr4.w * stride, cy + db4.w * stride);
    }
    float s0 = (bv.x > 0.05f) ? bv.x : 0.0f;
    float s1 = (bv.y > 0.05f) ? bv.y : 0.0f;
    float s2 = (bv.z > 0.05f) ? bv.z : 0.0f;
    float s3 = (bv.w > 0.05f) ? bv.w : 0.0f;
    *(float4*)&g_score[o] = make_float4(s0, s1, s2, s3);
    *(int4*)&g_kind[o]    = make_int4(k0, k1, k2, k3);

    unsigned* hb = &g_hist[b * NBIN];
    if (s0 > 0.0f) { int bn = (int)(s0 * (float)NBIN); if (bn > NBIN-1) bn = NBIN-1; atomicAdd(&hb[bn], 1u); }
    if (s1 > 0.0f) { int bn = (int)(s1 * (float)NBIN); if (bn > NBIN-1) bn = NBIN-1; atomicAdd(&hb[bn], 1u); }
    if (s2 > 0.0f) { int bn = (int)(s2 * (float)NBIN); if (bn > NBIN-1) bn = NBIN-1; atomicAdd(&hb[bn], 1u); }
    if (s3 > 0.0f) { int bn = (int)(s3 * (float)NBIN); if (bn > NBIN-1) bn = NBIN-1; atomicAdd(&hb[bn], 1u); }
}

// ---------------- K2: k_select — exact top-1000 via counting sort ------------
// smem: buf u64[2048] | buf2 u64[2048] | fineH u32[8192] | offs u32[8192] | gsum u32[1024]
#define SEL_BUF2  16384
#define SEL_FH    32768
#define SEL_OFF   65536
#define SEL_GS    98304
#define SEL_SMEM  102400

__global__ void __launch_bounds__(1024) k_select(float* __restrict__ out)
{
    const int b   = blockIdx.x;
    const int tid = threadIdx.x;

    extern __shared__ char sm[];
    unsigned long long* buf   = (unsigned long long*)sm;
    unsigned long long* buf2  = (unsigned long long*)(sm + SEL_BUF2);
    unsigned*           fineH = (unsigned*)(sm + SEL_FH);
    unsigned*           offs  = (unsigned*)(sm + SEL_OFF);
    unsigned*           gsum  = (unsigned*)(sm + SEL_GS);

    __shared__ unsigned ssum[32], sWarp[32];
    __shared__ int s_t, s_cnt;

    const unsigned* hb = &g_hist[b * NBIN];

    // phase T: threshold bin
    {
        unsigned s = 0;
        #pragma unroll
        for (int r = 0; r < 8; r++) {
            unsigned h = hb[NBIN - 1 - (8 * tid + r)];
            fineH[NBIN - 1 - (8 * tid + r)] = h;
            s += h;
        }
        gsum[tid] = s;
    }
    __syncthreads();
    if (tid < 32) {
        unsigned s = 0;
        #pragma unroll
        for (int q = 0; q < 32; q++) s += gsum[tid * 32 + q];
        ssum[tid] = s;
    }
    __syncthreads();
    if (tid == 0) {
        unsigned cum = 0;
        int t = 0;
        bool found = false;
        for (int w = 0; w < 32 && !found; w++) {
            if (cum + ssum[w] < KTOP) { cum += ssum[w]; continue; }
            for (int g = w * 32; g < w * 32 + 32 && !found; g++) {
                if (cum + gsum[g] < KTOP) { cum += gsum[g]; continue; }
                for (int r = g * 8; r < g * 8 + 8; r++) {
                    cum += fineH[NBIN - 1 - r];
                    if (cum >= KTOP) { t = NBIN - 1 - r; found = true; break; }
                }
            }
        }
        s_t = found ? t : 0;
        s_cnt = 0;
    }
    __syncthreads();
    const int   t     = s_t;
    const float lo    = (float)t * (1.0f / (float)NBIN);
    const float scale = (float)NBIN / (1.0f - lo + 1e-6f);

    // phase C: zero global hist; compact + fine hist
    for (int i = tid; i < NBIN; i += 1024) {
        g_hist[b * NBIN + i] = 0u;
        fineH[i] = 0u;
    }
    __syncthreads();
    const float* sc_base = &g_score[b * NPOS];
    for (int i = tid; i < NPOS; i += 1024) {
        float sc = sc_base[i];
        if (sc > 0.0f) {
            int bin = (int)(sc * (float)NBIN);
            if (bin > NBIN - 1) bin = NBIN - 1;
            if (bin >= t) {
                int k = atomicAdd(&s_cnt, 1);
                if (k < CAP) {
                    buf[k] = ((unsigned long long)__float_as_uint(sc) << 32) |
                             (unsigned long long)(0xFFFFFFFFu - (unsigned)i);
                    int fb = (int)((sc - lo) * scale);
                    fb = max(0, min(NBIN - 1, fb));
                    atomicAdd(&fineH[fb], 1u);
                }
            }
        }
    }
    __syncthreads();
    const int C = min(s_cnt, CAP);

    // phase S: exclusive scan over fine bins, descending
    unsigned c8[8];
    unsigned tsum = 0;
    #pragma unroll
    for (int r = 0; r < 8; r++) {
        int fb = NBIN - 1 - (tid * 8 + r);
        c8[r] = fineH[fb];
        tsum += c8[r];
    }
    {
        unsigned lane = tid & 31, wrp = tid >> 5;
        unsigned v = tsum;
        #pragma unroll
        for (int o = 1; o < 32; o <<= 1) {
            unsigned u = __shfl_up_sync(0xFFFFFFFFu, v, o);
            if (lane >= o) v += u;
        }
        unsigned wexcl = v - tsum;
        if (lane == 31) sWarp[wrp] = v;
        __syncthreads();
        if (tid < 32) {
            unsigned w0 = sWarp[tid];
            unsigned vv = w0;
            #pragma unroll
            for (int o = 1; o < 32; o <<= 1) {
                unsigned u = __shfl_up_sync(0xFFFFFFFFu, vv, o);
                if (tid >= (unsigned)o) vv += u;
            }
            sWarp[tid] = vv - w0;
        }
        __syncthreads();
        unsigned run = sWarp[wrp] + wexcl;
        #pragma unroll
        for (int r = 0; r < 8; r++) {
            int fb = NBIN - 1 - (tid * 8 + r);
            offs[fb] = run;
            run += c8[r];
        }
    }
    __syncthreads();

    // phase X: scatter
    for (int k = tid; k < C; k += 1024) {
        unsigned long long key = buf[k];
        float sc = __uint_as_float((unsigned)(key >> 32));
        int fb = (int)((sc - lo) * scale);
        fb = max(0, min(NBIN - 1, fb));
        unsigned slot = atomicAdd(&offs[fb], 1u);
        buf2[slot] = key;
    }
    __syncthreads();

    // phase F: intra-bin fixups
    for (int fb = tid; fb < NBIN; fb += 1024) {
        unsigned c = fineH[fb];
        if (c >= 2) {
            unsigned st = offs[fb] - c;
            for (unsigned a = st + 1; a < st + c; a++) {
                unsigned long long kv = buf2[a];
                unsigned p = a;
                while (p > st && buf2[p - 1] < kv) { buf2[p] = buf2[p - 1]; p--; }
                buf2[p] = kv;
            }
        }
    }
    __syncthreads();

    // emit cols 0..4 + stage NMS inputs
    if (tid < KTOP) {
        int i = tid;
        unsigned long long key = (i < C) ? buf2[i] : 0ULL;
        unsigned pos = 0xFFFFFFFFu - (unsigned)(key & 0xFFFFFFFFull);
        if (key == 0ULL) pos = 0;
        int src = b * NPOS + (int)pos;
        float4 bx = g_boxes[src];
        int    kd = g_kind[src];

        int row = b * KTOP + i;
        out[row * 6 + 0] = bx.x;
        out[row * 6 + 1] = bx.y;
        out[row * 6 + 2] = bx.z;
        out[row * 6 + 3] = bx.w;
        out[row * 6 + 4] = (float)kd;

        g_topBox[row]   = bx;
        g_topKind[row]  = kd;
        g_topScore[row] = (key != 0ULL) ? __uint_as_float((unsigned)(key >> 32)) : 0.0f;
    }
}

// ---------------- K3: k_nms — mask build + Jacobi fixpoint greedy ------------
// smem: mask u32[1000*33] | sx1/sy1/sx2/sy2/sar f32[1000] + skd i32[1000]
//       | rowNZ u32[1000] | kindBits u32[80*32]
#define NMS_X1  132000
#define NMS_Y1  136000
#define NMS_X2  140000
#define NMS_Y2  144000
#define NMS_AR  148000
#define NMS_KD  152000
#define NMS_NZ  156000
#define NMS_KB  160000
#define NMS_SMEM 170240

__global__ void __launch_bounds__(1024) k_nms(float* __restrict__ out)
{
    const int b    = blockIdx.x;
    const int tid  = threadIdx.x;
    const int wid  = tid >> 5;
    const int lane = tid & 31;

    extern __shared__ char sm[];
    unsigned* mask     = (unsigned*)sm;
    float*    sx1      = (float*)(sm + NMS_X1);
    float*    sy1      = (float*)(sm + NMS_Y1);
    float*    sx2      = (float*)(sm + NMS_X2);
    float*    sy2      = (float*)(sm + NMS_Y2);
    float*    sar      = (float*)(sm + NMS_AR);
    int*      skd      = (int*)(sm + NMS_KD);
    unsigned* rowNZ    = (unsigned*)(sm + NMS_NZ);
    unsigned* kindBits = (unsigned*)(sm + NMS_KB);

    __shared__ unsigned remA[32], remB[32];
    __shared__ int s_changed;

    for (int i = tid; i < NCLS * 32; i += 1024) kindBits[i] = 0u;
    if (tid < KTOP) rowNZ[tid] = 0u;
    if (tid < 32) remA[tid] = 0u;
    __syncthreads();

    if (tid < KTOP) {
        int i = tid;
        int row = b * KTOP + i;
        float4 bx = g_topBox[row];
        int kd    = g_topKind[row];
        sx1[i] = bx.x; sy1[i] = bx.y; sx2[i] = bx.z; sy2[i] = bx.w;
        sar[i] = fmaxf(bx.z - bx.x, 0.0f) * fmaxf(bx.w - bx.y, 0.0f);
        skd[i] = kd;
        atomicOr(&kindBits[kd * 32 + (i >> 5)], 1u << (i & 31));
    }
    __syncthreads();

    // suppression bitmask (padded pitch), row-nonzero flags inline
    for (int task = tid; task < KTOP * 32; task += 1024) {
        int i = task >> 5;
        int w = task & 31;
        int kd = skd[i];
        unsigned cand = kindBits[kd * 32 + w];
        int iw = i >> 5;
        if (w < iw)       cand = 0u;
        else if (w == iw) cand &= ~((2u << (i & 31)) - 1u);
        unsigned bits = 0u;
        if (cand) {
            float x1 = sx1[i], y1 = sy1[i], x2 = sx2[i], y2 = sy2[i], ai = sar[i];
            do {
                int jj = __ffs(cand) - 1;
                cand &= cand - 1u;
                int j = w * 32 + jj;
                float xx1 = fmaxf(x1, sx1[j]);
                float yy1 = fmaxf(y1, sy1[j]);
                float xx2 = fminf(x2, sx2[j]);
                float yy2 = fminf(y2, sy2[j]);
                float inter = fmaxf(xx2 - xx1, 0.0f) * fmaxf(yy2 - yy1, 0.0f);
                float iou = inter / (((ai + sar[j]) - inter) + 1e-9f);
                if (iou > IOU_TH) bits |= (1u << jj);
            } while (cand);
        }
        mask[i * MPITCH + w] = bits;
        if (bits) rowNZ[i] = 1u;   // benign race: all writers store 1
    }
    __syncthreads();

    // Jacobi fixpoint: removed = OR_{j kept} mask[j].  Forward-only DAG =>
    // unique fixpoint == sequential greedy; converges in chain-depth+1 rounds.
    for (int round = 0; round < KTOP; round++) {
        if (tid < 32) remB[tid] = 0u;
        if (tid == 0) s_changed = 0;
        __syncthreads();
        for (int r = wid; r < KTOP; r += 32) {
            if (rowNZ[r] && !((remA[r >> 5] >> (r & 31)) & 1u)) {
                unsigned mw = mask[r * MPITCH + lane];
                if (mw) atomicOr(&remB[lane], mw);
            }
        }
        __syncthreads();
        if (tid < 32 && remB[tid] != remA[tid]) s_changed = 1;
        __syncthreads();
        if (!s_changed) break;
        if (tid < 32) remA[tid] = remB[tid];
        __syncthreads();
    }

    // final scores
    if (tid < KTOP) {
        int i = tid;
        bool kept = !((remA[i >> 5] >> (i & 31)) & 1u);
        float sc = g_topScore[b * KTOP + i];
        out[(b * KTOP + i) * 6 + 5] = (kept && sc > 0.0f) ? sc : 0.0f;
    }
}

// ---------------- launch ----------------
extern "C" void kernel_launch(void* const* d_in, const int* in_sizes, int n_in,
                              void* d_out, int out_size)
{
    static const int hw[5] = { 16384, 4096, 1024, 256, 64 };
    const float* clsP[5] = { 0, 0, 0, 0, 0 };
    const float* regP[5] = { 0, 0, 0, 0, 0 };
    bool cntSeen[5] = { false, false, false, false, false };

    for (int i = 0; i < n_in; i++) {
        long long s = in_sizes[i];
        bool matched = false;
        for (int l = 0; l < 5 && !matched; l++)
            if (s == (long long)NB * NCLS * hw[l]) { clsP[l] = (const float*)d_in[i]; matched = true; }
        if (matched) continue;
        for (int l = 0; l < 5 && !matched; l++)
            if (s == (long long)NB * hw[l] && !cntSeen[l]) { cntSeen[l] = true; matched = true; }
        if (matched) continue;
        for (int l = 0; l < 5 && !matched; l++)
            if (s == (long long)NB * 4 * hw[l] && !regP[l]) { regP[l] = (const float*)d_in[i]; matched = true; }
    }

    float* out = (float*)d_out;

    cudaFuncSetAttribute(k_select, cudaFuncAttributeMaxDynamicSharedMemorySize, SEL_SMEM);
    cudaFuncSetAttribute(k_nms,    cudaFuncAttributeMaxDynamicSharedMemorySize, NMS_SMEM);

    dim3 g1((NG + 127) / 128, NB);
    k_decode<<<g1, 128>>>(clsP[0], clsP[1], clsP[2], clsP[3], clsP[4],
                          regP[0], regP[1], regP[2], regP[3], regP[4]);
    k_select<<<NB, 1024, SEL_SMEM>>>(out);
    k_nms   <<<NB, 1024, NMS_SMEM>>>(out);
}